// round 17
// baseline (speedup 1.0000x reference)
#include <cuda_runtime.h>
#include <math.h>
#include <stdint.h>

#define BATCH 32
#define NIN   1024
#define NC    20
#define DIM   64
#define CD    (NC*DIM)   // 1280
#define CIN   128

// ---------------- scratch (device globals: no allocations allowed) ----------
__device__ float g_uhat[(size_t)BATCH * NIN * CD];   // 167.8 MB
__device__ float g_bij[BATCH * NIN * NC];            // routing logits
__device__ float g_spart[BATCH * NC * DIM];          // partial weighted sums (zeroed by squash)
__device__ float g_wsum[BATCH * NC];                 // partial weight sums
__device__ float g_v[BATCH * NC * DIM];              // v per iteration
__device__ float g_vn2[BATCH * NC];                  // |v|^2 per (b,class)

// ---------------- packed f32x2 helpers --------------------------------------
__device__ __forceinline__ void ffma2(unsigned long long &d,
                                      unsigned long long a,
                                      unsigned long long b) {
    asm("fma.rn.f32x2 %0, %1, %2, %0;" : "+l"(d) : "l"(a), "l"(b));
}
__device__ __forceinline__ float2 upk(unsigned long long v) {
    float2 f;
    asm("mov.b64 {%0, %1}, %2;" : "=f"(f.x), "=f"(f.y) : "l"(v));
    return f;
}
__device__ __forceinline__ void cp16(uint32_t dst, const float* src) {
    asm volatile("cp.async.cg.shared.global [%0], [%1], 16;\n"
                 :: "r"(dst), "l"(src));
}
#define CP_COMMIT() asm volatile("cp.async.commit_group;\n" ::: "memory")
#define CP_WAIT1()  asm volatile("cp.async.wait_group 1;\n" ::: "memory")

// per-warp w ring: 16 rows/chunk. Stage = 4 cq-groups x (8 pieces x 16B =
// 128B) + 16B pad = 144B/group -> 576B/stage; cq stride 144 == 16 mod 128
// -> the 4 consumer LDS.128 addresses hit distinct bank quads.
#define GCQ_B     144
#define GSTAGE_B  (4 * GCQ_B)           // 576 bytes
#define GSTAGE_F  (GSTAGE_B / 4)        // 144 floats
#define GRING_F   (3 * GSTAGE_F)        // 432 floats per warp

// ---------------- Kernel 0: no-op (ncu alignment: puts k_gemm at index 3) ---
__global__ void k_nop() {}

// ---------------- Kernel 1: u_hat GEMM (4b x 4cd tile, 3 blocks/SM) ---------
// grid = (CD/128 = 10, NIN), block = 256 (8 warps).
// Block: one n, all 32 b, 128 consecutive cd rows. Warp w owns 16 rows
// [w*16, w*16+16). Thread tile: 4 b x 4 cd (bg = t&7, b = bi*8+bg;
// cg = t>>3, rows cdBase + cg*4 + r). Halved accumulators (32 regs) let
// 3 blocks/SM run (24 warps) -- the R15 profile showed 16 warps leave the
// fma pipe at 43% with nothing saturated (latency-bound).
// Producer: one cp.async per lane per chunk (lane -> row = lane>>1,
// half = lane&1); 16 distinct 128B gmem lines per instruction.
// Consumer inner offsets are compile-time immediates (pad layout).
__global__ __launch_bounds__(256, 3)
void k_gemm(const float* __restrict__ x, const float* __restrict__ w1) {
    __shared__ __align__(16) float xs[32 * 132];          // 16.9 KB
    __shared__ __align__(16) float wsm[8 * GRING_F];      // 13.5 KB

    const int n      = blockIdx.y;
    const int cdBase = blockIdx.x * 128;
    const int t      = threadIdx.x;
    const int w      = t >> 5;
    const int lane   = t & 31;

    // stage x[:, n, :]  (32 x 128) into smem, coalesced (x is L2-resident)
    for (int e = t; e < 32 * 128; e += 256) {
        int bb = e >> 7, i = e & 127;
        xs[bb * 132 + i] = x[((size_t)bb * NIN + n) * CIN + i];
    }
    __syncthreads();

    // producer mapping: lane -> (row = lane>>1 in 0..15, half = lane&1)
    const int rowp = lane >> 1;
    const int half = lane & 1;
    const float* wrow = w1 + ((size_t)n * CD + cdBase + w * 16 + rowp) * CIN + half * 4;
    uint32_t wb = (uint32_t)__cvta_generic_to_shared(&wsm[w * GRING_F]);
    // dst: cq = rowp>>2, piece s = (rowp&3)*2 + half at byte cq*144 + s*16
    const uint32_t dA = wb + (uint32_t)((rowp >> 2) * GCQ_B
                                        + ((rowp & 3) * 2 + half) * 16);

    // prologue: chunks 0,1 in flight
    cp16(dA,            wrow + 0);  CP_COMMIT();
    cp16(dA + GSTAGE_B, wrow + 8);  CP_COMMIT();

    const int bg = t & 7;
    const int cg = t >> 3;          // 0..31 block-wide
    const int cq = cg & 3;

    unsigned long long acc[4][4];
    #pragma unroll
    for (int bi = 0; bi < 4; bi++)
        #pragma unroll
        for (int r = 0; r < 4; r++) acc[bi][r] = 0ull;

    // hoisted consumer base: this thread's cq block within its warp's ring
    const float* wbase = &wsm[w * GRING_F] + cq * (GCQ_B / 4);

    int stC = 0;   // stage holding chunk ks
    int stP = 2;   // stage to refill with chunk ks+2
    #pragma unroll 1
    for (int ks = 0; ks < 16; ks++) {
        CP_WAIT1();            // chunk ks resident in stage stC
        __syncwarp();

        // leading refill: chunk ks+2 into the stage consumed at iter ks-1
        if (ks + 2 < 16) {
            cp16(dA + stP * GSTAGE_B, wrow + (ks + 2) * 8);
        }
        CP_COMMIT();           // one group per iteration (possibly empty)

        const float* wt = wbase + stC * GSTAGE_F;

        #pragma unroll
        for (int q = 0; q < 2; q++) {
            const int i0 = ks * 8 + q * 4;
            ulonglong2 xq[4];
            #pragma unroll
            for (int bi = 0; bi < 4; bi++)
                xq[bi] = *(const ulonglong2*)(xs + (bi * 8 + bg) * 132 + i0);
            #pragma unroll
            for (int r = 0; r < 4; r++) {
                // offset (r*2+q)*16B: compile-time immediate
                ulonglong2 wq = *(const ulonglong2*)(wt + (r * 2 + q) * 4);
                #pragma unroll
                for (int bi = 0; bi < 4; bi++) {
                    ffma2(acc[bi][r], xq[bi].x, wq.x);
                    ffma2(acc[bi][r], xq[bi].y, wq.y);
                }
            }
        }

        stC = (stC == 2) ? 0 : stC + 1;
        stP = (stP == 2) ? 0 : stP + 1;
    }

    // epilogue: horizontal add of packed pairs, one float4 store per bi
    #pragma unroll
    for (int bi = 0; bi < 4; bi++) {
        const int b = bi * 8 + bg;
        float o[4];
        #pragma unroll
        for (int r = 0; r < 4; r++) {
            float2 f = upk(acc[bi][r]);
            o[r] = f.x + f.y;
        }
        float* op = g_uhat + ((size_t)b * NIN + n) * CD + cdBase + cg * 4;
        *(float4*)(op) = make_float4(o[0], o[1], o[2], o[3]);
    }
}

// ---------------- Kernel 1b: iteration-0 weighted sum -----------------------
// With b_ij = 0, c collapses to exactly 1/1024 for every (n, class), so
// s0[b,c,d] = sum_n u_hat / 1024. Pure streaming reduction, no softmax pass.
// grid = (CD/256 = 5, BATCH, 8 n-segments), block = 256.
__global__ __launch_bounds__(256)
void k_sum0() {
    const int cd = blockIdx.x * 256 + threadIdx.x;
    const int b  = blockIdx.y;
    const int n0 = blockIdx.z * 128;

    const float* p = g_uhat + ((size_t)b * NIN + n0) * CD + cd;
    float s0 = 0.f, s1 = 0.f, s2 = 0.f, s3 = 0.f;
    #pragma unroll 4
    for (int k = 0; k < 128; k += 4) {
        s0 += p[(size_t)(k + 0) * CD];
        s1 += p[(size_t)(k + 1) * CD];
        s2 += p[(size_t)(k + 2) * CD];
        s3 += p[(size_t)(k + 3) * CD];
    }
    atomicAdd(&g_spart[b * CD + cd], (s0 + s1) + (s2 + s3));

    if (blockIdx.x == 0 && blockIdx.z == 0 && threadIdx.x < NC)
        g_wsum[b * NC + threadIdx.x] = 1024.0f;
}

// ---------------- Kernel 2: fused routing pass (iters 1,2; R11 known-good) --
__global__ __launch_bounds__(256)
void k_route(int iter) {
    __shared__ float v_s[CD];
    __shared__ float vn2_s[NC];
    __shared__ float sbuf[8][CD];
    __shared__ float wbuf[8][NC];

    const int b  = blockIdx.y;
    const int n0 = blockIdx.x * 32;
    const int t    = threadIdx.x;
    const int w    = t >> 5;
    const int lane = t & 31;

    for (int e = t; e < CD; e += 256) v_s[e] = g_v[b * CD + e];
    if (t < NC) vn2_s[t] = g_vn2[b * NC + t];
    __syncthreads();

    float2 sacc[NC];
    #pragma unroll
    for (int j = 0; j < NC; j++) sacc[j] = make_float2(0.f, 0.f);
    float cwacc = 0.f;

    for (int k = 0; k < 4; k++) {
        const int n = n0 + k * 8 + w;
        const float* up = g_uhat + ((size_t)b * NIN + n) * CD;

        float2 ur[NC];
        float myun2 = 0.f, mydot = 0.f;

        #pragma unroll
        for (int j = 0; j < NC; j++) {
            float2 u2 = *(const float2*)(up + j * DIM + 2 * lane);
            ur[j] = u2;
            float2 v2 = *(const float2*)(v_s + j * DIM + 2 * lane);
            float p = u2.x * u2.x + u2.y * u2.y;
            float q = u2.x * v2.x + u2.y * v2.y;
            #pragma unroll
            for (int off = 16; off > 0; off >>= 1) {
                p += __shfl_xor_sync(0xffffffffu, p, off);
                q += __shfl_xor_sync(0xffffffffu, q, off);
            }
            if (lane == j) { myun2 = p; mydot = q; }
        }

        float bnew = -3.0e38f;
        if (lane < NC) {
            float un2 = myun2;
            float a   = sqrtf(un2) / (0.5f + un2);          // squash scale of u_hat
            float dd  = 1.0f - (a * a * un2 - 2.0f * a * mydot + vn2_s[lane]);
            if (iter == 1) {
                bnew = dd;                                    // b was 0
                g_bij[(b * NIN + n) * NC + lane] = dd;
            } else {
                bnew = g_bij[(b * NIN + n) * NC + lane] + dd; // last iter: no store needed
            }
        }
        float m = bnew;
        #pragma unroll
        for (int off = 16; off > 0; off >>= 1)
            m = fmaxf(m, __shfl_xor_sync(0xffffffffu, m, off));
        float e = (lane < NC) ? __expf(bnew - m) : 0.0f;
        float ssum = e;
        #pragma unroll
        for (int off = 16; off > 0; off >>= 1)
            ssum += __shfl_xor_sync(0xffffffffu, ssum, off);
        float craw = e / ssum;

        // accumulate weighted sums (u_hat reused from registers)
        #pragma unroll
        for (int j = 0; j < NC; j++) {
            float cj = __shfl_sync(0xffffffffu, craw, j);
            sacc[j].x += cj * ur[j].x;
            sacc[j].y += cj * ur[j].y;
        }
        if (lane < NC) cwacc += craw;
    }

    // stage per-warp partials, block-reduce, one atomic per element per block
    #pragma unroll
    for (int j = 0; j < NC; j++)
        *(float2*)&sbuf[w][j * DIM + 2 * lane] = sacc[j];
    if (lane < NC) wbuf[w][lane] = cwacc;
    __syncthreads();

    for (int e = t; e < CD; e += 256) {
        float s = 0.f;
        #pragma unroll
        for (int ww = 0; ww < 8; ww++) s += sbuf[ww][e];
        atomicAdd(&g_spart[b * CD + e], s);
    }
    if (t < NC) {
        float s = 0.f;
        #pragma unroll
        for (int ww = 0; ww < 8; ww++) s += wbuf[ww][t];
        atomicAdd(&g_wsum[b * NC + t], s);
    }
}

// ---------------- Kernel 3: squash + (final) output --------------------------
__global__ __launch_bounds__(64)
void k_squash(int final_iter, float* __restrict__ out) {
    const int bj = blockIdx.x;          // b*NC + j
    const int d  = threadIdx.x;
    const int lane = d & 31, wp = d >> 5;

    float sv = g_spart[bj * DIM + d];
    float ws = g_wsum[bj];
    float s  = sv / ws;

    float p = s * s;
    #pragma unroll
    for (int off = 16; off > 0; off >>= 1)
        p += __shfl_xor_sync(0xffffffffu, p, off);
    __shared__ float red[2];
    if (lane == 0) red[wp] = p;
    __syncthreads();
    float s2 = red[0] + red[1];

    float sc = sqrtf(s2) / (0.5f + s2);
    float v  = sc * s;

    g_v[bj * DIM + d] = v;
    if (d == 0) g_vn2[bj] = sc * sc * s2;

    // reset partials so next iteration / next graph replay starts clean
    g_spart[bj * DIM + d] = 0.0f;
    if (d == 0) g_wsum[bj] = 0.0f;

    if (final_iter) {
        out[bj * DIM + d] = v;                                  // poses [B,C,D,1] flattened
        if (d == 0)
            out[BATCH * NC * DIM + bj] = sqrtf(sc * sc * s2);   // activations [B,C,1]
    }
}

// ---------------- launch -----------------------------------------------------
extern "C" void kernel_launch(void* const* d_in, const int* in_sizes, int n_in,
                              void* d_out, int out_size) {
    const float* x  = (const float*)d_in[0];
    const float* w1 = (const float*)d_in[1];
    if (n_in >= 2 && in_sizes[0] > in_sizes[1]) {   // defensive: x is the smaller input
        x  = (const float*)d_in[1];
        w1 = (const float*)d_in[0];
    }
    float* out = (float*)d_out;

    // 3 no-op launches keep k_gemm at our launch index 3 = the ncu window.
    for (int i = 0; i < 3; i++) k_nop<<<1, 32>>>();

    k_gemm<<<dim3(CD / 128, NIN), 256>>>(x, w1);

    k_sum0<<<dim3(CD / 256, BATCH, 8), 256>>>();
    k_squash<<<BATCH * NC, 64>>>(0, out);

    k_route<<<dim3(NIN / 32, BATCH), 256>>>(1);
    k_squash<<<BATCH * NC, 64>>>(0, out);

    k_route<<<dim3(NIN / 32, BATCH), 256>>>(2);
    k_squash<<<BATCH * NC, 64>>>(1, out);
}